// round 5
// baseline (speedup 1.0000x reference)
#include <cuda_runtime.h>
#include <cuda_fp16.h>
#include <cstdint>

#define N_OUT 4096
#define M_IN  4096
#define BATCH 128
#define KTOT  4096
#define BN    64
#define SPLITK 4
#define KPER  (KTOT / SPLITK)   // 1024
#define BK    64
#define KT    (KPER / BK)       // 16
#define STAGES 4
// stage size in halves: A 128x64 + B 64x64 = 12288 halves (24KB)
#define STG_H 12288
#define SMEM_BYTES (STAGES * STG_H * 2)   // 98304

// Scratch (device globals; no allocation allowed)
__device__ __align__(16) __half g_Wh[(size_t)N_OUT * M_IN];   // 32MB dense fp16 W
__device__ __align__(16) __half g_xh[BATCH * M_IN];           // x in fp16

// ---------------------------------------------------------------------------
__device__ __forceinline__ uint32_t smem_u32(const void* p) {
    return (uint32_t)__cvta_generic_to_shared(p);
}
__device__ __forceinline__ void cpasync16(uint32_t dst, const void* src) {
    asm volatile("cp.async.cg.shared.global [%0], [%1], 16;" :: "r"(dst), "l"(src));
}
__device__ __forceinline__ void ldsm4(uint32_t* r, uint32_t a) {
    asm volatile("ldmatrix.sync.aligned.m8n8.x4.shared.b16 {%0,%1,%2,%3}, [%4];"
                 : "=r"(r[0]), "=r"(r[1]), "=r"(r[2]), "=r"(r[3]) : "r"(a));
}
__device__ __forceinline__ void ldsm2(uint32_t* r, uint32_t a) {
    asm volatile("ldmatrix.sync.aligned.m8n8.x2.shared.b16 {%0,%1}, [%2];"
                 : "=r"(r[0]), "=r"(r[1]) : "r"(a));
}
__device__ __forceinline__ void mma16816(float* c, const uint32_t* a, const uint32_t* b) {
    asm volatile(
        "mma.sync.aligned.m16n8k16.row.col.f32.f16.f16.f32 "
        "{%0,%1,%2,%3}, {%4,%5,%6,%7}, {%8,%9}, {%0,%1,%2,%3};"
        : "+f"(c[0]), "+f"(c[1]), "+f"(c[2]), "+f"(c[3])
        : "r"(a[0]), "r"(a[1]), "r"(a[2]), "r"(a[3]), "r"(b[0]), "r"(b[1]));
}
__device__ __forceinline__ void redv2(float* p, float x, float y) {
    asm volatile("red.global.add.v2.f32 [%0], {%1, %2};"
                 :: "l"(p), "f"(x), "f"(y) : "memory");
}

// ---------------------------------------------------------------------------
// K0 (fused): zero W, convert x -> fp16, init out with bias
// ---------------------------------------------------------------------------
__global__ void k_prep(const float* __restrict__ x,
                       const float* __restrict__ bias,
                       float* __restrict__ out) {
    const int gid = blockIdx.x * blockDim.x + threadIdx.x;
    const int nthr = gridDim.x * blockDim.x;   // 1,048,576

    // zero W: 2,097,152 uint4 chunks -> 2 per thread
    uint4* wp = reinterpret_cast<uint4*>(g_Wh);
    uint4 z; z.x = 0; z.y = 0; z.z = 0; z.w = 0;
    const int n4 = (int)(((size_t)N_OUT * M_IN) / 8);
    for (int i = gid; i < n4; i += nthr) wp[i] = z;

    // x conversion + out=bias: 4 elements per thread, first 131072 threads
    if (gid < (BATCH * M_IN) / 4) {
        const int idx = gid * 4;
        float4 v = *reinterpret_cast<const float4*>(x + idx);
        __half2* xp = reinterpret_cast<__half2*>(g_xh + idx);
        xp[0] = __floats2half2_rn(v.x, v.y);
        xp[1] = __floats2half2_rn(v.z, v.w);
        *reinterpret_cast<float4*>(out + idx) =
            *reinterpret_cast<const float4*>(bias + (idx & (N_OUT - 1)));
    }
}

// ---------------------------------------------------------------------------
// K1: scatter quantized values into dense fp16 W (duplicates accumulate)
// 4 nnz per thread via int4 loads (NNZ = 1638400 is divisible by 4)
// ---------------------------------------------------------------------------
__global__ void k_scatter(const int* __restrict__ val,
                          const int* __restrict__ rows,
                          const int* __restrict__ cols,
                          int nnz4) {
    int i = blockIdx.x * blockDim.x + threadIdx.x;
    if (i < nnz4) {
        int4 v = reinterpret_cast<const int4*>(val)[i];
        int4 r = reinterpret_cast<const int4*>(rows)[i];
        int4 c = reinterpret_cast<const int4*>(cols)[i];
        atomicAdd(&g_Wh[(size_t)r.x * M_IN + c.x], __float2half_rn((float)v.x));
        atomicAdd(&g_Wh[(size_t)r.y * M_IN + c.y], __float2half_rn((float)v.y));
        atomicAdd(&g_Wh[(size_t)r.z * M_IN + c.z], __float2half_rn((float)v.z));
        atomicAdd(&g_Wh[(size_t)r.w * M_IN + c.w], __float2half_rn((float)v.w));
    }
}

// ---------------------------------------------------------------------------
// K2: GEMM  out[b,n] += scale[n] * sum_k x_h[b,k] * W[n,k]
// CTA tile 128(batch) x 64(N), BK=64, 4-stage cp.async, split-K=4.
// 8 warps as 4(m) x 2(n); warp tile 32x32. Register fragments double-buffered
// across the 4 k16 sub-steps; cp.async for stage kt+3 issued BEFORE the wait.
// ---------------------------------------------------------------------------
__global__ void __launch_bounds__(256, 2)
k_gemm(const float* __restrict__ scales, float* __restrict__ out) {
    extern __shared__ __align__(1024) __half sm[];

    const int tid  = threadIdx.x;
    const int lane = tid & 31;
    const int warp = tid >> 5;
    const int wm   = warp & 3;       // 0..3  -> 32-row M strip
    const int wn   = warp >> 2;      // 0..1  -> 32-col N strip
    const int bn0  = blockIdx.x * BN;
    const int kbase = blockIdx.y * KPER;

    float acc[2][4][4];
#pragma unroll
    for (int i = 0; i < 2; i++)
#pragma unroll
        for (int j = 0; j < 4; j++)
#pragma unroll
            for (int q = 0; q < 4; q++) acc[i][j][q] = 0.0f;

    // per-thread load coords: 4 A chunks, 2 B chunks of 16B each
    uint32_t aoff[4], boff[2];
    const __half* asrc[4];
    const __half* bsrc[2];
#pragma unroll
    for (int i = 0; i < 4; i++) {
        int q = tid + i * 256;           // 0..1023
        int r = q >> 3, c = q & 7;
        aoff[i] = (r * 64 + ((c ^ (r & 7)) << 3)) * 2;   // byte offset
        asrc[i] = g_xh + r * M_IN + kbase + (c << 3);
    }
#pragma unroll
    for (int i = 0; i < 2; i++) {
        int q = tid + i * 256;           // 0..511
        int r = q >> 3, c = q & 7;
        boff[i] = (8192 + r * 64 + ((c ^ (r & 7)) << 3)) * 2;
        bsrc[i] = g_Wh + (size_t)(bn0 + r) * M_IN + kbase + (c << 3);
    }

    const uint32_t smb = smem_u32(sm);

    auto load_stage = [&](int s, int kofs) {
        uint32_t sb = smb + s * (STG_H * 2);
#pragma unroll
        for (int i = 0; i < 4; i++) cpasync16(sb + aoff[i], asrc[i] + kofs);
#pragma unroll
        for (int i = 0; i < 2; i++) cpasync16(sb + boff[i], bsrc[i] + kofs);
    };

    // fragment smem addresses (depend only on lane/warp, not kt)
    // A: row fixed per mi; chunk = ks*2 + (lane>>4)
    // B: row fixed per ni; chunk = ks*2 + ((lane>>3)&1)
    uint32_t a_rowaddr[2], b_rowaddr[4];
    int a_chsel = lane >> 4;             // 0..1
    int b_chsel = (lane >> 3) & 1;       // 0..1
#pragma unroll
    for (int mi = 0; mi < 2; mi++) {
        int row = wm * 32 + mi * 16 + (lane & 7) + ((lane >> 3) & 1) * 8;
        a_rowaddr[mi] = row * 64 * 2;    // byte offset of row base (pre-swizzle)
    }
#pragma unroll
    for (int ni = 0; ni < 4; ni++) {
        int rowb = wn * 32 + ni * 8 + (lane & 7);
        b_rowaddr[ni] = (8192 + rowb * 64) * 2;
    }
    // swizzle helpers need the row's (r&7); recompute:
    int a_r7[2], b_r7[4];
#pragma unroll
    for (int mi = 0; mi < 2; mi++) {
        int row = wm * 32 + mi * 16 + (lane & 7) + ((lane >> 3) & 1) * 8;
        a_r7[mi] = row & 7;
    }
#pragma unroll
    for (int ni = 0; ni < 4; ni++) {
        int rowb = wn * 32 + ni * 8 + (lane & 7);
        b_r7[ni] = rowb & 7;
    }

    // prologue: stages 0..2
#pragma unroll
    for (int s = 0; s < STAGES - 1; s++) {
        load_stage(s, s * BK);
        asm volatile("cp.async.commit_group;");
    }

    uint32_t af[2][2][4];   // [buf][mi][4]
    uint32_t bf[2][4][2];   // [buf][ni][2]

#pragma unroll 1
    for (int kt = 0; kt < KT; ++kt) {
        // issue stage kt+3 loads first, then wait for stage kt (<=3 pending)
        if (kt + STAGES - 1 < KT)
            load_stage((kt + STAGES - 1) & (STAGES - 1), (kt + STAGES - 1) * BK);
        asm volatile("cp.async.commit_group;");
        asm volatile("cp.async.wait_group %0;" :: "n"(STAGES - 1));
        __syncthreads();

        const uint32_t st = smb + (kt & (STAGES - 1)) * (STG_H * 2);

        // preload fragments for ks=0 into buffer 0
#pragma unroll
        for (int mi = 0; mi < 2; mi++) {
            int ch = a_chsel;   // ks=0
            ldsm4(af[0][mi], st + a_rowaddr[mi] + (((ch ^ a_r7[mi]) << 3) * 2));
        }
#pragma unroll
        for (int ni = 0; ni < 4; ni++) {
            int ch = b_chsel;   // ks=0
            ldsm2(bf[0][ni], st + b_rowaddr[ni] + (((ch ^ b_r7[ni]) << 3) * 2));
        }

#pragma unroll
        for (int ks = 0; ks < 4; ++ks) {
            const int cur = ks & 1, nxt = cur ^ 1;
            if (ks < 3) {
#pragma unroll
                for (int mi = 0; mi < 2; mi++) {
                    int ch = (ks + 1) * 2 + a_chsel;
                    ldsm4(af[nxt][mi], st + a_rowaddr[mi] + (((ch ^ a_r7[mi]) << 3) * 2));
                }
#pragma unroll
                for (int ni = 0; ni < 4; ni++) {
                    int ch = (ks + 1) * 2 + b_chsel;
                    ldsm2(bf[nxt][ni], st + b_rowaddr[ni] + (((ch ^ b_r7[ni]) << 3) * 2));
                }
            }
#pragma unroll
            for (int ni = 0; ni < 4; ni++)
#pragma unroll
                for (int mi = 0; mi < 2; mi++)
                    mma16816(acc[mi][ni], af[cur][mi], bf[cur][ni]);
        }
        __syncthreads();
    }

    // epilogue: scale + atomic add into bias-initialized out
#pragma unroll
    for (int ni = 0; ni < 4; ni++) {
        int nq = bn0 + wn * 32 + ni * 8 + ((lane & 3) << 1);
        float s0 = __ldg(scales + nq);
        float s1 = __ldg(scales + nq + 1);
#pragma unroll
        for (int mi = 0; mi < 2; mi++) {
            int r0 = wm * 32 + mi * 16 + (lane >> 2);
            redv2(out + (size_t)r0 * N_OUT + nq,
                  acc[mi][ni][0] * s0, acc[mi][ni][1] * s1);
            redv2(out + (size_t)(r0 + 8) * N_OUT + nq,
                  acc[mi][ni][2] * s0, acc[mi][ni][3] * s1);
        }
    }
}

// ---------------------------------------------------------------------------
extern "C" void kernel_launch(void* const* d_in, const int* in_sizes, int n_in,
                              void* d_out, int out_size) {
    const float* x    = (const float*)d_in[0];
    const int*   wval = (const int*)d_in[1];
    const float* wsc  = (const float*)d_in[2];
    const int*   rows = (const int*)d_in[3];
    const int*   cols = (const int*)d_in[4];
    const float* bias = (const float*)d_in[5];
    float* out = (float*)d_out;
    const int nnz = in_sizes[1];
    const int nnz4 = nnz / 4;

    cudaFuncSetAttribute(k_gemm, cudaFuncAttributeMaxDynamicSharedMemorySize, SMEM_BYTES);

    k_prep<<<4096, 256>>>(x, bias, out);
    k_scatter<<<(nnz4 + 255) / 256, 256>>>(wval, rows, cols, nnz4);
    k_gemm<<<dim3(N_OUT / BN, SPLITK), 256, SMEM_BYTES>>>(wsc, out);
}